// round 17
// baseline (speedup 1.0000x reference)
#include <cuda_runtime.h>
#include <cstdint>

typedef unsigned long long ull;

// Problem constants
#define L_DIM   2048
#define N_B     2
#define E_DIM   1024
#define H_N     16
#define D_H     64
#define S_DIM   2048
#define K_SEL   1176              // int(2048 * sigmoid(0.3))
#define T_SEL   (S_DIM - K_SEL)   // 872: 0-based ascending rank of threshold

// Scratch (static device arrays are allowed; cudaMalloc is not)
__device__ float g_Qp[4096 * 1024];     // [n][h][l][d]
__device__ float g_Kp[4096 * 1024];     // [n][h][l][d]
__device__ float g_Vp[4096 * 1024];     // [n][h][l][d]
__device__ float g_O [4096 * 1024];     // [(l,n)][d*16+h]
__device__ float g_S [67108864];        // [h][l][s] scores for ONE n (256 MB)

// ---------------------------------------------------------------------------
// Helpers
// ---------------------------------------------------------------------------
__device__ __forceinline__ unsigned f2key(float f) {
    unsigned u = __float_as_uint(f);
    return (u & 0x80000000u) ? ~u : (u | 0x80000000u);
}
__device__ __forceinline__ float key2f(unsigned k) {
    unsigned u = (k & 0x80000000u) ? (k ^ 0x80000000u) : ~k;
    return __uint_as_float(u);
}
// Fast e^x for x <= 0 (poly exp2, ~1e-7 rel err). Avoids MUFU bottleneck.
__device__ __forceinline__ float fexp(float x) {
    float y = x * 1.4426950408889634f;
    y = fmaxf(y, -120.0f);
    float fl = floorf(y);
    float f  = y - fl;
    float p  =             1.53533619e-4f;
    p = fmaf(p, f, 1.33988744e-3f);
    p = fmaf(p, f, 9.61843736e-3f);
    p = fmaf(p, f, 5.55033247e-2f);
    p = fmaf(p, f, 2.40226479e-1f);
    p = fmaf(p, f, 6.93147203e-1f);
    p = fmaf(p, f, 1.0f);
    return p * __int_as_float(((int)fl + 127) << 23);
}

// --- packed f32x2 ops (Blackwell, sm_100+) ---
__device__ __forceinline__ ull pk2(float a, float b) {
    ull r;
    asm("mov.b64 %0, {%1, %2};" : "=l"(r) : "r"(__float_as_uint(a)), "r"(__float_as_uint(b)));
    return r;
}
__device__ __forceinline__ ull fma2(ull a, ull b, ull c) {
    ull d;
    asm("fma.rn.f32x2 %0, %1, %2, %3;" : "=l"(d) : "l"(a), "l"(b), "l"(c));
    return d;
}
__device__ __forceinline__ float2 upk(ull v) {
    unsigned lo, hi;
    asm("mov.b64 {%0, %1}, %2;" : "=r"(lo), "=r"(hi) : "l"(v));
    return make_float2(__uint_as_float(lo), __uint_as_float(hi));
}

// ---------------------------------------------------------------------------
// Projection GEMM: C = A[4096,1024] @ W^T + bias. SCATTER=true writes the
// result into [n][h][l][d] layout; false writes row-major (final output).
// BM=BN=128, BK=16, 256 threads, 8x8 micro via 32 FFMA2, reg prefetch.
// A tile stored DUPLICATED in smem (dup cols 2i,2i+1 = orig col i) so the
// compute loop reads FFMA2-ready dup'd operands with zero pk2 moves.
// ---------------------------------------------------------------------------
template <bool SCATTER>
__device__ __forceinline__
void gemm_body(const float* __restrict__ A, const float* __restrict__ B,
               const float* __restrict__ bias, float* __restrict__ C,
               int bm, int bn)
{
    __shared__ __align__(16) float As[16 * 256];   // dup'd: [k][2*row]
    __shared__ __align__(16) float Bs[16 * 128];
    const int tid = threadIdx.x;
    const int ty = tid >> 4, tx = tid & 15;
    const int rr = tid >> 2, k4 = tid & 3;

    ull acc[8][4];
#pragma unroll
    for (int i = 0; i < 8; ++i)
#pragma unroll
        for (int j = 0; j < 4; ++j) acc[i][j] = 0ull;

    const float* Abase = A + (size_t)(bm * 128 + rr) * 1024 + k4 * 4;
    const float* Bbase = B + (size_t)(bn * 128 + rr) * 1024 + k4 * 4;

    float4 pa0 = *(const float4*)(Abase);
    float4 pa1 = *(const float4*)(Abase + (size_t)64 * 1024);
    float4 pb0 = *(const float4*)(Bbase);
    float4 pb1 = *(const float4*)(Bbase + (size_t)64 * 1024);

    for (int kt = 0; kt < 64; ++kt) {
        // A: duplicated stores (dup col = 2*orig col)
        *(float2*)(As + (k4 * 4 + 0) * 256 + rr * 2) = make_float2(pa0.x, pa0.x);
        *(float2*)(As + (k4 * 4 + 1) * 256 + rr * 2) = make_float2(pa0.y, pa0.y);
        *(float2*)(As + (k4 * 4 + 2) * 256 + rr * 2) = make_float2(pa0.z, pa0.z);
        *(float2*)(As + (k4 * 4 + 3) * 256 + rr * 2) = make_float2(pa0.w, pa0.w);
        *(float2*)(As + (k4 * 4 + 0) * 256 + rr * 2 + 128) = make_float2(pa1.x, pa1.x);
        *(float2*)(As + (k4 * 4 + 1) * 256 + rr * 2 + 128) = make_float2(pa1.y, pa1.y);
        *(float2*)(As + (k4 * 4 + 2) * 256 + rr * 2 + 128) = make_float2(pa1.z, pa1.z);
        *(float2*)(As + (k4 * 4 + 3) * 256 + rr * 2 + 128) = make_float2(pa1.w, pa1.w);
        Bs[(k4 * 4 + 0) * 128 + rr] = pb0.x;
        Bs[(k4 * 4 + 1) * 128 + rr] = pb0.y;
        Bs[(k4 * 4 + 2) * 128 + rr] = pb0.z;
        Bs[(k4 * 4 + 3) * 128 + rr] = pb0.w;
        Bs[(k4 * 4 + 0) * 128 + rr + 64] = pb1.x;
        Bs[(k4 * 4 + 1) * 128 + rr + 64] = pb1.y;
        Bs[(k4 * 4 + 2) * 128 + rr + 64] = pb1.z;
        Bs[(k4 * 4 + 3) * 128 + rr + 64] = pb1.w;
        __syncthreads();

        if (kt < 63) {
            const int off = (kt + 1) * 16;
            pa0 = *(const float4*)(Abase + off);
            pa1 = *(const float4*)(Abase + (size_t)64 * 1024 + off);
            pb0 = *(const float4*)(Bbase + off);
            pb1 = *(const float4*)(Bbase + (size_t)64 * 1024 + off);
        }

#pragma unroll
        for (int k = 0; k < 16; ++k) {
            const ulonglong2 aa0 = *(const ulonglong2*)(As + k * 256 + ty * 8);
            const ulonglong2 aa1 = *(const ulonglong2*)(As + k * 256 + ty * 8 + 4);
            const ulonglong2 aa2 = *(const ulonglong2*)(As + k * 256 + 128 + ty * 8);
            const ulonglong2 aa3 = *(const ulonglong2*)(As + k * 256 + 128 + ty * 8 + 4);
            const ulonglong2 bpa = *(const ulonglong2*)(Bs + k * 128 + tx * 4);
            const ulonglong2 bpb = *(const ulonglong2*)(Bs + k * 128 + 64 + tx * 4);
            const ull ad[8] = {aa0.x, aa0.y, aa1.x, aa1.y, aa2.x, aa2.y, aa3.x, aa3.y};
            const ull bp[4] = {bpa.x, bpa.y, bpb.x, bpb.y};
#pragma unroll
            for (int ii = 0; ii < 8; ++ii)
#pragma unroll
                for (int jj = 0; jj < 4; ++jj)
                    acc[ii][jj] = fma2(ad[ii], bp[jj], acc[ii][jj]);
        }
        __syncthreads();
    }
    // Epilogue with bias
#pragma unroll
    for (int jh = 0; jh < 2; ++jh) {
        const int col = bn * 128 + jh * 64 + tx * 4;
        const float4 bb = *(const float4*)(bias + col);
#pragma unroll
        for (int ii = 0; ii < 8; ++ii) {
            const int row = bm * 128 + ((ii < 4) ? (ty * 4 + ii) : (64 + ty * 4 + ii - 4));
            const float2 c01 = upk(acc[ii][jh * 2 + 0]);
            const float2 c23 = upk(acc[ii][jh * 2 + 1]);
            float4 o;
            o.x = c01.x + bb.x;
            o.y = c01.y + bb.y;
            o.z = c23.x + bb.z;
            o.w = c23.y + bb.w;
            if (SCATTER) {
                // row=(l,n), col=(h,d) -> [n][h][l][d]
                const int l = row >> 1, nn = row & 1;
                const int h = bn * 2 + jh, d = tx * 4;
                *(float4*)(C + ((size_t)(nn * 16 + h) * 2048 + l) * 64 + d) = o;
            } else {
                *(float4*)(C + (size_t)row * 1024 + col) = o;
            }
        }
    }
}

__global__ __launch_bounds__(256, 2)
void gemm_qkv_kernel(const float* __restrict__ q, const float* __restrict__ k,
                     const float* __restrict__ v,
                     const float* __restrict__ Wq, const float* __restrict__ bq,
                     const float* __restrict__ Wk, const float* __restrict__ bk,
                     const float* __restrict__ Wv, const float* __restrict__ bv,
                     float* __restrict__ Qp, float* __restrict__ Kp, float* __restrict__ Vp)
{
    const int which = blockIdx.z;
    const float* A    = (which == 0) ? q  : (which == 1) ? k  : v;
    const float* B    = (which == 0) ? Wq : (which == 1) ? Wk : Wv;
    const float* bias = (which == 0) ? bq : (which == 1) ? bk : bv;
    float*       C    = (which == 0) ? Qp : (which == 1) ? Kp : Vp;
    gemm_body<true>(A, B, bias, C, blockIdx.y, blockIdx.x);
}

__global__ __launch_bounds__(256, 2)
void gemm_o_kernel(const float* __restrict__ A, const float* __restrict__ B,
                   const float* __restrict__ bias, float* __restrict__ C)
{
    gemm_body<false>(A, B, bias, C, blockIdx.y, blockIdx.x);
}

// ---------------------------------------------------------------------------
// QK^T for one n: per-h GEMM  S[2048,2048] = Q[2048,64] @ K^T * 0.125
// BM=BN=128, BK=16 x4, 256 threads. Same dup'd-A scheme as gemm_body.
// ---------------------------------------------------------------------------
__global__ __launch_bounds__(256, 2)
void qk_kernel(int n)
{
    __shared__ __align__(16) float As[16 * 256];   // dup'd
    __shared__ __align__(16) float Bs[16 * 128];
    const int tid = threadIdx.x;
    const int h = blockIdx.z, bm = blockIdx.y, bn = blockIdx.x;
    const int nh = n * 16 + h;
    const int ty = tid >> 4, tx = tid & 15;
    const int rr = tid >> 2, k4 = tid & 3;

    const float* A = g_Qp + (size_t)nh * 131072;  // 2048*64
    const float* B = g_Kp + (size_t)nh * 131072;

    ull acc[8][4];
#pragma unroll
    for (int i = 0; i < 8; ++i)
#pragma unroll
        for (int j = 0; j < 4; ++j) acc[i][j] = 0ull;

    const float* Abase = A + (size_t)(bm * 128 + rr) * 64 + k4 * 4;
    const float* Bbase = B + (size_t)(bn * 128 + rr) * 64 + k4 * 4;

    float4 pa0 = *(const float4*)(Abase);
    float4 pa1 = *(const float4*)(Abase + 64 * 64);
    float4 pb0 = *(const float4*)(Bbase);
    float4 pb1 = *(const float4*)(Bbase + 64 * 64);

#pragma unroll
    for (int kt = 0; kt < 4; ++kt) {
        *(float2*)(As + (k4 * 4 + 0) * 256 + rr * 2) = make_float2(pa0.x, pa0.x);
        *(float2*)(As + (k4 * 4 + 1) * 256 + rr * 2) = make_float2(pa0.y, pa0.y);
        *(float2*)(As + (k4 * 4 + 2) * 256 + rr * 2) = make_float2(pa0.z, pa0.z);
        *(float2*)(As + (k4 * 4 + 3) * 256 + rr * 2) = make_float2(pa0.w, pa0.w);
        *(float2*)(As + (k4 * 4 + 0) * 256 + rr * 2 + 128) = make_float2(pa1.x, pa1.x);
        *(float2*)(As + (k4 * 4 + 1) * 256 + rr * 2 + 128) = make_float2(pa1.y, pa1.y);
        *(float2*)(As + (k4 * 4 + 2) * 256 + rr * 2 + 128) = make_float2(pa1.z, pa1.z);
        *(float2*)(As + (k4 * 4 + 3) * 256 + rr * 2 + 128) = make_float2(pa1.w, pa1.w);
        Bs[(k4 * 4 + 0) * 128 + rr] = pb0.x;
        Bs[(k4 * 4 + 1) * 128 + rr] = pb0.y;
        Bs[(k4 * 4 + 2) * 128 + rr] = pb0.z;
        Bs[(k4 * 4 + 3) * 128 + rr] = pb0.w;
        Bs[(k4 * 4 + 0) * 128 + rr + 64] = pb1.x;
        Bs[(k4 * 4 + 1) * 128 + rr + 64] = pb1.y;
        Bs[(k4 * 4 + 2) * 128 + rr + 64] = pb1.z;
        Bs[(k4 * 4 + 3) * 128 + rr + 64] = pb1.w;
        __syncthreads();

        if (kt < 3) {
            const int off = (kt + 1) * 16;
            pa0 = *(const float4*)(Abase + off);
            pa1 = *(const float4*)(Abase + 64 * 64 + off);
            pb0 = *(const float4*)(Bbase + off);
            pb1 = *(const float4*)(Bbase + 64 * 64 + off);
        }

#pragma unroll
        for (int k = 0; k < 16; ++k) {
            const ulonglong2 aa0 = *(const ulonglong2*)(As + k * 256 + ty * 8);
            const ulonglong2 aa1 = *(const ulonglong2*)(As + k * 256 + ty * 8 + 4);
            const ulonglong2 aa2 = *(const ulonglong2*)(As + k * 256 + 128 + ty * 8);
            const ulonglong2 aa3 = *(const ulonglong2*)(As + k * 256 + 128 + ty * 8 + 4);
            const ulonglong2 bpa = *(const ulonglong2*)(Bs + k * 128 + tx * 4);
            const ulonglong2 bpb = *(const ulonglong2*)(Bs + k * 128 + 64 + tx * 4);
            const ull ad[8] = {aa0.x, aa0.y, aa1.x, aa1.y, aa2.x, aa2.y, aa3.x, aa3.y};
            const ull bp[4] = {bpa.x, bpa.y, bpb.x, bpb.y};
#pragma unroll
            for (int ii = 0; ii < 8; ++ii)
#pragma unroll
                for (int jj = 0; jj < 4; ++jj)
                    acc[ii][jj] = fma2(ad[ii], bp[jj], acc[ii][jj]);
        }
        __syncthreads();
    }
    // Epilogue: scale by 1/sqrt(64) and write scores
    float* Sbase = g_S + (size_t)h * 4194304;
#pragma unroll
    for (int jh = 0; jh < 2; ++jh) {
        const int col = bn * 128 + jh * 64 + tx * 4;
#pragma unroll
        for (int ii = 0; ii < 8; ++ii) {
            const int row = bm * 128 + ((ii < 4) ? (ty * 4 + ii) : (64 + ty * 4 + ii - 4));
            const float2 c01 = upk(acc[ii][jh * 2 + 0]);
            const float2 c23 = upk(acc[ii][jh * 2 + 1]);
            float4 o;
            o.x = c01.x * 0.125f;
            o.y = c01.y * 0.125f;
            o.z = c23.x * 0.125f;
            o.w = c23.y * 0.125f;
            *(float4*)(Sbase + (size_t)row * 2048 + col) = o;
        }
    }
}

// ---------------------------------------------------------------------------
// Select + softmax: one 256-thread block per score row (32768 blocks/pass).
// Row cached in registers. Pass b=3 uses warp-aggregated atomics (exponent
// byte -> heavy bin conflicts); passes b=2..0 use plain predicated atomics.
// ---------------------------------------------------------------------------
__global__ __launch_bounds__(256)
void sel_kernel()
{
    __shared__ unsigned hist[256];
    __shared__ unsigned s_pfx, s_T, s_km;
    __shared__ float    f_red[8];
    __shared__ unsigned u_red[8];
    __shared__ float    s_inv;

    const int tid = threadIdx.x, lane = tid & 31, wid = tid >> 5;
    float* srow = g_S + (size_t)blockIdx.x * 2048;

    float v[8];
    unsigned key[8];
    {
        const float4 f0 = *(const float4*)(srow + tid * 8);
        const float4 f1 = *(const float4*)(srow + tid * 8 + 4);
        v[0] = f0.x; v[1] = f0.y; v[2] = f0.z; v[3] = f0.w;
        v[4] = f1.x; v[5] = f1.y; v[6] = f1.z; v[7] = f1.w;
#pragma unroll
        for (int i = 0; i < 8; ++i) key[i] = f2key(v[i]);
    }

    // block max of keys
    {
        unsigned km = key[0];
#pragma unroll
        for (int i = 1; i < 8; ++i) km = (key[i] > km) ? key[i] : km;
#pragma unroll
        for (int o = 16; o > 0; o >>= 1) {
            const unsigned t = __shfl_xor_sync(0xffffffffu, km, o);
            km = (t > km) ? t : km;
        }
        if (lane == 0) u_red[wid] = km;
        __syncthreads();
        if (tid == 0) {
            unsigned m = u_red[0];
#pragma unroll
            for (int i = 1; i < 8; ++i) m = (u_red[i] > m) ? u_red[i] : m;
            s_km = m;
        }
    }

    unsigned prefix = 0, T = T_SEL;

    // ---- pass b=3: all 2048 keys; warp-aggregated (few distinct exp bins) ----
    {
        hist[tid] = 0;
        __syncthreads();
#pragma unroll
        for (int i = 0; i < 8; ++i) {
            const unsigned bin = key[i] >> 24;
            const unsigned grp = __match_any_sync(0xffffffffu, bin);
            if (lane == (__ffs(grp) - 1))
                atomicAdd(&hist[bin], (unsigned)__popc(grp));
        }
        __syncthreads();
        if (wid == 0) {
            unsigned c[8], lsum = 0;
#pragma unroll
            for (int i = 0; i < 8; ++i) { c[i] = hist[lane * 8 + i]; lsum += c[i]; }
            unsigned inc = lsum;
#pragma unroll
            for (int o = 1; o < 32; o <<= 1) {
                const unsigned t = __shfl_up_sync(0xffffffffu, inc, o);
                if (lane >= o) inc += t;
            }
            const unsigned exl = inc - lsum;
            if (T >= exl && T < exl + lsum) {
                unsigned cum = exl;
#pragma unroll
                for (int i = 0; i < 8; ++i) {
                    if (T < cum + c[i]) {
                        s_pfx = (unsigned)(lane * 8 + i) << 24;
                        s_T   = T - cum;
                        break;
                    }
                    cum += c[i];
                }
            }
        }
        __syncthreads();
        prefix = s_pfx;
        T = s_T;
        __syncthreads();
    }

    // ---- passes b=2..0: only prefix-matching keys; plain atomics ----
#pragma unroll
    for (int b = 2; b >= 0; --b) {
        hist[tid] = 0;
        __syncthreads();
        const unsigned himask = 0xFFFFFFFFu << ((b + 1) * 8);
#pragma unroll
        for (int i = 0; i < 8; ++i) {
            if ((key[i] & himask) == prefix)
                atomicAdd(&hist[(key[i] >> (b * 8)) & 255], 1u);
        }
        __syncthreads();
        if (wid == 0) {
            unsigned c[8], lsum = 0;
#pragma unroll
            for (int i = 0; i < 8; ++i) { c[i] = hist[lane * 8 + i]; lsum += c[i]; }
            unsigned inc = lsum;
#pragma unroll
            for (int o = 1; o < 32; o <<= 1) {
                const unsigned t = __shfl_up_sync(0xffffffffu, inc, o);
                if (lane >= o) inc += t;
            }
            const unsigned exl = inc - lsum;
            if (T >= exl && T < exl + lsum) {
                unsigned cum = exl;
#pragma unroll
                for (int i = 0; i < 8; ++i) {
                    if (T < cum + c[i]) {
                        s_pfx = prefix | ((unsigned)(lane * 8 + i) << (b * 8));
                        s_T   = T - cum;
                        break;
                    }
                    cum += c[i];
                }
            }
        }
        __syncthreads();
        prefix = s_pfx;
        T = s_T;
        __syncthreads();
    }

    // masked exp + block sum
    const unsigned tk = prefix;
    const float m = key2f(s_km);
    float w[8];
    float lsum = 0.0f;
#pragma unroll
    for (int i = 0; i < 8; ++i) {
        w[i] = (key[i] >= tk) ? fexp(v[i] - m) : 0.0f;
        lsum += w[i];
    }
#pragma unroll
    for (int o = 16; o > 0; o >>= 1)
        lsum += __shfl_xor_sync(0xffffffffu, lsum, o);
    if (lane == 0) f_red[wid] = lsum;
    __syncthreads();
    if (tid == 0) {
        float t = 0.0f;
#pragma unroll
        for (int i = 0; i < 8; ++i) t += f_red[i];
        s_inv = 1.0f / t;
    }
    __syncthreads();
    const float inv = s_inv;

    float4 o0 = make_float4(w[0] * inv, w[1] * inv, w[2] * inv, w[3] * inv);
    float4 o1 = make_float4(w[4] * inv, w[5] * inv, w[6] * inv, w[7] * inv);
    *(float4*)(srow + tid * 8)     = o0;
    *(float4*)(srow + tid * 8 + 4) = o1;
}

// ---------------------------------------------------------------------------
// PV for one n: per-h GEMM  O[2048,64] = W[2048,2048] @ V[2048,64]
// BM=64, BK=64, 256 threads, 4l x 4d micro via FFMA2 (measured-good pattern).
// Wt transposed (stride 65); W reads warp-broadcast. smem 33KB -> 4 blocks/SM
// (launch_bounds(256,4)); grid 32x16 = 512 blocks = single wave at occ 4.
// Output scattered to g_O[(l,n)][d*16+h] for the O projection.
// ---------------------------------------------------------------------------
#define PV_LSTR 65
#define PV_SMEM_BYTES ((64 * PV_LSTR + 64 * 64) * 4)

__global__ __launch_bounds__(256, 4)
void pv_kernel(int n)
{
    extern __shared__ float psm[];
    float* Wt = psm;                // [64 s][PV_LSTR l] (transposed)
    float* Vs = psm + 64 * PV_LSTR; // [64 s][64 d]

    const int tid = threadIdx.x;
    const int h = blockIdx.y, bm = blockIdx.x;
    const int nh = n * 16 + h;
    const int ty = tid >> 4, tx = tid & 15;   // ty: l quad (0..15), tx: d quad

    const float* Wrow  = g_S + (size_t)h * 4194304 + (size_t)bm * 64 * 2048;
    const float* Vbase = g_Vp + (size_t)nh * 131072;

    ull acc[2][4];
#pragma unroll
    for (int i = 0; i < 2; ++i)
#pragma unroll
        for (int j = 0; j < 4; ++j) acc[i][j] = 0ull;

    for (int kt = 0; kt < 32; ++kt) {
        // W tile [64 l][64 s] -> transposed Wt[s][l]
#pragma unroll
        for (int i = 0; i < 4; ++i) {
            const int idx = i * 256 + tid;
            const int lr = idx >> 4, sq = idx & 15;
            const float4 w = *(const float4*)(Wrow + (size_t)lr * 2048 + kt * 64 + sq * 4);
            Wt[(sq * 4 + 0) * PV_LSTR + lr] = w.x;
            Wt[(sq * 4 + 1) * PV_LSTR + lr] = w.y;
            Wt[(sq * 4 + 2) * PV_LSTR + lr] = w.z;
            Wt[(sq * 4 + 3) * PV_LSTR + lr] = w.w;
        }
        // V tile [64 s][64 d]
#pragma unroll
        for (int i = 0; i < 4; ++i) {
            const int idx = i * 256 + tid;
            const int sr = idx >> 4, d4 = idx & 15;
            *(float4*)(Vs + sr * 64 + d4 * 4) =
                *(const float4*)(Vbase + (size_t)(kt * 64 + sr) * 64 + d4 * 4);
        }
        __syncthreads();

        const float* wb = Wt + ty * 4;
        const float* vb = Vs + tx * 4;
#pragma unroll 4
        for (int s = 0; s < 64; ++s) {
            const float* wr = wb + s * PV_LSTR;   // W[l = ty*4 .. ty*4+3][s]
            const ull p0 = pk2(wr[0], wr[1]);
            const ull p1 = pk2(wr[2], wr[3]);
            const float4 vv = *(const float4*)(vb + s * 64);
            const ull v0 = pk2(vv.x, vv.x);
            const ull v1 = pk2(vv.y, vv.y);
            const ull v2 = pk2(vv.z, vv.z);
            const ull v3 = pk2(vv.w, vv.w);
            acc[0][0] = fma2(p0, v0, acc[0][0]);
            acc[0][1] = fma2(p0, v1, acc[0][1]);
            acc[0][2] = fma2(p0, v2, acc[0][2]);
            acc[0][3] = fma2(p0, v3, acc[0][3]);
            acc[1][0] = fma2(p1, v0, acc[1][0]);
            acc[1][1] = fma2(p1, v1, acc[1][1]);
            acc[1][2] = fma2(p1, v2, acc[1][2]);
            acc[1][3] = fma2(p1, v3, acc[1][3]);
        }
        __syncthreads();
    }

    // Epilogue: scatter to g_O[(l,n)][d*16+h]
#pragma unroll
    for (int lp = 0; lp < 2; ++lp) {
        const int l0 = bm * 64 + ty * 4 + lp * 2;
        float* o0 = g_O + (size_t)(l0 * 2 + n) * 1024 + h;
        float* o1 = g_O + (size_t)((l0 + 1) * 2 + n) * 1024 + h;
#pragma unroll
        for (int j = 0; j < 4; ++j) {
            const float2 r = upk(acc[lp][j]);
            const int d = tx * 4 + j;
            o0[d * 16] = r.x;
            o1[d * 16] = r.y;
        }
    }
}

// ---------------------------------------------------------------------------
// Launch
// ---------------------------------------------------------------------------
extern "C" void kernel_launch(void* const* d_in, const int* in_sizes, int n_in,
                              void* d_out, int out_size)
{
    (void)in_sizes; (void)n_in; (void)out_size;
    const float* query = (const float*)d_in[0];
    const float* key   = (const float*)d_in[1];
    const float* value = (const float*)d_in[2];
    const float* Wq = (const float*)d_in[3];
    const float* bq = (const float*)d_in[4];
    const float* Wk = (const float*)d_in[5];
    const float* bk = (const float*)d_in[6];
    const float* Wv = (const float*)d_in[7];
    const float* bv = (const float*)d_in[8];
    const float* Wo = (const float*)d_in[9];
    const float* bo = (const float*)d_in[10];

    float *Qp, *Kp, *Vp, *O;
    cudaGetSymbolAddress((void**)&Qp, g_Qp);
    cudaGetSymbolAddress((void**)&Kp, g_Kp);
    cudaGetSymbolAddress((void**)&Vp, g_Vp);
    cudaGetSymbolAddress((void**)&O,  g_O);

    cudaFuncSetAttribute(pv_kernel, cudaFuncAttributeMaxDynamicSharedMemorySize,
                         PV_SMEM_BYTES);

    gemm_qkv_kernel<<<dim3(8, 32, 3), 256>>>(query, key, value,
                                             Wq, bq, Wk, bk, Wv, bv,
                                             Qp, Kp, Vp);

    for (int n = 0; n < N_B; ++n) {
        qk_kernel<<<dim3(16, 16, 16), 256>>>(n);
        sel_kernel<<<32768, 256>>>();
        pv_kernel<<<dim3(32, 16), 256, PV_SMEM_BYTES>>>(n);
    }

    gemm_o_kernel<<<dim3(8, 32), 256>>>(O, Wo, bo, (float*)d_out);
}